// round 1
// baseline (speedup 1.0000x reference)
#include <cuda_runtime.h>
#include <cstddef>

// Problem constants
// x: [16][32][128][128] fp32 -> X[2][256][16384]
// Wq: [512][256], Wkv: [1024][256], Wout: [256][512], bout: [256]
// out: [2][256][16384] fp32

#define NSEQ 16384
#define GQKV_M 1536

// Scratch (static __device__ -> allowed; no runtime allocation)
__device__ float g_qkv [(size_t)2 * 1536 * 16384];   // Q[512],K[512],V[512] per group
__device__ float g_part[(size_t)16 * 32 * 64 * 64];  // sim partials (32 k-splits)
__device__ float g_attn[(size_t)16 * 64 * 64];       // softmax(sim)
__device__ float g_outm[(size_t)2 * 512 * 16384];    // attn @ V

// ---------------------------------------------------------------------------
// Kernel 1: QKV[g] = [Wq;Wkv] @ X[g]     (M=1536, K=256, N=16384, batch g=2)
// 64x64 tile, BK=16, 256 threads, 4x4 per thread.
// ---------------------------------------------------------------------------
__global__ void __launch_bounds__(256) gemm_qkv(const float* __restrict__ x,
                                                const float* __restrict__ Wq,
                                                const float* __restrict__ Wkv)
{
    const int n0 = blockIdx.x * 64;
    const int m0 = blockIdx.y * 64;
    const int g  = blockIdx.z;

    // Row block is entirely inside Wq or Wkv (64 | 512).
    const float* W = (m0 < 512) ? (Wq + (size_t)m0 * 256)
                                : (Wkv + (size_t)(m0 - 512) * 256);
    const float* B = x + (size_t)g * 256 * NSEQ;
    float*       C = g_qkv + (size_t)g * GQKV_M * NSEQ;

    __shared__ float As[16][64];
    __shared__ float Bs[16][64];

    const int tid = threadIdx.x;
    const int tx = tid & 15, ty = tid >> 4;

    // load mapping
    const int ar = tid >> 2;         // 0..63  (m within tile)
    const int ac = (tid & 3) * 4;    // 0,4,8,12 (k within tile)
    const int br = tid >> 4;         // 0..15  (k within tile)
    const int bc = (tid & 15) * 4;   // 0..60  (n within tile)

    float acc[4][4] = {};

    for (int kk = 0; kk < 256; kk += 16) {
        float4 av = *reinterpret_cast<const float4*>(&W[(size_t)ar * 256 + kk + ac]);
        float4 bv = *reinterpret_cast<const float4*>(&B[(size_t)(kk + br) * NSEQ + n0 + bc]);
        __syncthreads();
        As[ac + 0][ar] = av.x; As[ac + 1][ar] = av.y;
        As[ac + 2][ar] = av.z; As[ac + 3][ar] = av.w;
        *reinterpret_cast<float4*>(&Bs[br][bc]) = bv;
        __syncthreads();
#pragma unroll
        for (int k = 0; k < 16; ++k) {
            float4 a = *reinterpret_cast<const float4*>(&As[k][ty * 4]);
            float4 b = *reinterpret_cast<const float4*>(&Bs[k][tx * 4]);
            float ra[4] = {a.x, a.y, a.z, a.w};
            float rb[4] = {b.x, b.y, b.z, b.w};
#pragma unroll
            for (int i = 0; i < 4; ++i)
#pragma unroll
                for (int j = 0; j < 4; ++j)
                    acc[i][j] = fmaf(ra[i], rb[j], acc[i][j]);
        }
    }

#pragma unroll
    for (int i = 0; i < 4; ++i) {
        const int m = m0 + ty * 4 + i;
        float4 o = make_float4(acc[i][0], acc[i][1], acc[i][2], acc[i][3]);
        *reinterpret_cast<float4*>(&C[(size_t)m * NSEQ + n0 + tx * 4]) = o;
    }
}

// ---------------------------------------------------------------------------
// Kernel 2: sim partials. For head bh, k-split ks (512 p each):
//   part[bh][ks][i][j] = sum_{p in split} Q[bh][i][p] * K[bh][j][p]
// ---------------------------------------------------------------------------
__global__ void __launch_bounds__(256) sim_kernel()
{
    const int ks = blockIdx.x;   // 0..31
    const int bh = blockIdx.y;   // 0..15
    const int g = bh >> 3, h = bh & 7;

    const float* Q = g_qkv + ((size_t)g * GQKV_M + h * 64) * NSEQ;
    const float* K = g_qkv + ((size_t)g * GQKV_M + 512 + h * 64) * NSEQ;
    const int p0 = ks * 512;

    __shared__ float Qs[16][64];
    __shared__ float Ks[16][64];

    const int tid = threadIdx.x;
    const int tx = tid & 15, ty = tid >> 4;
    const int lr = tid >> 2;        // row (i or j) 0..63
    const int lc = (tid & 3) * 4;   // p offset 0,4,8,12

    float acc[4][4] = {};

    for (int pp = 0; pp < 512; pp += 16) {
        float4 qv = *reinterpret_cast<const float4*>(&Q[(size_t)lr * NSEQ + p0 + pp + lc]);
        float4 kv = *reinterpret_cast<const float4*>(&K[(size_t)lr * NSEQ + p0 + pp + lc]);
        __syncthreads();
        Qs[lc + 0][lr] = qv.x; Qs[lc + 1][lr] = qv.y;
        Qs[lc + 2][lr] = qv.z; Qs[lc + 3][lr] = qv.w;
        Ks[lc + 0][lr] = kv.x; Ks[lc + 1][lr] = kv.y;
        Ks[lc + 2][lr] = kv.z; Ks[lc + 3][lr] = kv.w;
        __syncthreads();
#pragma unroll
        for (int k = 0; k < 16; ++k) {
            float4 a = *reinterpret_cast<const float4*>(&Qs[k][ty * 4]);
            float4 b = *reinterpret_cast<const float4*>(&Ks[k][tx * 4]);
            float ra[4] = {a.x, a.y, a.z, a.w};
            float rb[4] = {b.x, b.y, b.z, b.w};
#pragma unroll
            for (int i = 0; i < 4; ++i)
#pragma unroll
                for (int j = 0; j < 4; ++j)
                    acc[i][j] = fmaf(ra[i], rb[j], acc[i][j]);
        }
    }

    float* P = g_part + (((size_t)bh * 32 + ks) * 64) * 64;
#pragma unroll
    for (int i = 0; i < 4; ++i) {
        float4 o = make_float4(acc[i][0], acc[i][1], acc[i][2], acc[i][3]);
        *reinterpret_cast<float4*>(&P[(size_t)(ty * 4 + i) * 64 + tx * 4]) = o;
    }
}

// ---------------------------------------------------------------------------
// Kernel 3: reduce partials + scale + softmax over j.
// grid (64, 16): block = (row i, head bh), 64 threads = j.
// ---------------------------------------------------------------------------
__global__ void __launch_bounds__(64) softmax_kernel()
{
    const int i  = blockIdx.x;
    const int bh = blockIdx.y;
    const int j  = threadIdx.x;

    const float* P = g_part + (size_t)bh * 32 * 64 * 64;
    float v = 0.f;
#pragma unroll 8
    for (int ks = 0; ks < 32; ++ks)
        v += P[(size_t)(ks * 64 + i) * 64 + j];
    v *= 0.125f;  // DIM_HEAD^{-0.5}

    __shared__ float s[64];
    __shared__ float red;
    s[j] = v;
    __syncthreads();
    if (j == 0) {
        float m = s[0];
        for (int t = 1; t < 64; ++t) m = fmaxf(m, s[t]);
        red = m;
    }
    __syncthreads();
    const float e = __expf(v - red);
    s[j] = e;
    __syncthreads();
    if (j == 0) {
        float su = 0.f;
        for (int t = 0; t < 64; ++t) su += s[t];
        red = su;
    }
    __syncthreads();
    g_attn[((size_t)bh * 64 + i) * 64 + j] = e / red;
}

// ---------------------------------------------------------------------------
// Kernel 4: outm[bh][i][p] = sum_j attn[bh][i][j] * V[bh][j][p]
// grid (128, 16), 128 threads; thread owns one p column.
// ---------------------------------------------------------------------------
__global__ void __launch_bounds__(128) outm_kernel()
{
    const int bh = blockIdx.y;
    const int g = bh >> 3, h = bh & 7;
    const int p = blockIdx.x * 128 + threadIdx.x;

    __shared__ float a_s[64 * 64];
    const float* A = g_attn + (size_t)bh * 4096;
    for (int t = threadIdx.x; t < 4096; t += 128) a_s[t] = A[t];
    __syncthreads();

    const float* V = g_qkv + ((size_t)g * GQKV_M + 1024 + h * 64) * NSEQ;
    float v[64];
#pragma unroll
    for (int j = 0; j < 64; ++j) v[j] = V[(size_t)j * NSEQ + p];

    float* O = g_outm + ((size_t)g * 512 + h * 64) * NSEQ;
#pragma unroll 4
    for (int i = 0; i < 64; ++i) {
        float acc = 0.f;
#pragma unroll
        for (int j = 0; j < 64; ++j)
            acc = fmaf(a_s[i * 64 + j], v[j], acc);
        O[(size_t)i * NSEQ + p] = acc;
    }
}

// ---------------------------------------------------------------------------
// Kernel 5: Y[g] = Wout @ OutM[g] + bout   (M=256, K=512, N=16384)
// ---------------------------------------------------------------------------
__global__ void __launch_bounds__(256) gemm_out(const float* __restrict__ Wout,
                                                const float* __restrict__ bout,
                                                float* __restrict__ out)
{
    const int n0 = blockIdx.x * 64;
    const int m0 = blockIdx.y * 64;
    const int g  = blockIdx.z;

    const float* A = Wout;                              // [256][512]
    const float* B = g_outm + (size_t)g * 512 * NSEQ;   // [512][16384]
    float*       C = out + (size_t)g * 256 * NSEQ;

    __shared__ float As[16][64];
    __shared__ float Bs[16][64];

    const int tid = threadIdx.x;
    const int tx = tid & 15, ty = tid >> 4;
    const int ar = tid >> 2;
    const int ac = (tid & 3) * 4;
    const int br = tid >> 4;
    const int bc = (tid & 15) * 4;

    float acc[4][4] = {};

    for (int kk = 0; kk < 512; kk += 16) {
        float4 av = *reinterpret_cast<const float4*>(&A[(size_t)(m0 + ar) * 512 + kk + ac]);
        float4 bv = *reinterpret_cast<const float4*>(&B[(size_t)(kk + br) * NSEQ + n0 + bc]);
        __syncthreads();
        As[ac + 0][ar] = av.x; As[ac + 1][ar] = av.y;
        As[ac + 2][ar] = av.z; As[ac + 3][ar] = av.w;
        *reinterpret_cast<float4*>(&Bs[br][bc]) = bv;
        __syncthreads();
#pragma unroll
        for (int k = 0; k < 16; ++k) {
            float4 a = *reinterpret_cast<const float4*>(&As[k][ty * 4]);
            float4 b = *reinterpret_cast<const float4*>(&Bs[k][tx * 4]);
            float ra[4] = {a.x, a.y, a.z, a.w};
            float rb[4] = {b.x, b.y, b.z, b.w};
#pragma unroll
            for (int i = 0; i < 4; ++i)
#pragma unroll
                for (int j = 0; j < 4; ++j)
                    acc[i][j] = fmaf(ra[i], rb[j], acc[i][j]);
        }
    }

#pragma unroll
    for (int i = 0; i < 4; ++i) {
        const int m = m0 + ty * 4 + i;
        const float bb = bout[m];
        float4 o = make_float4(acc[i][0] + bb, acc[i][1] + bb,
                               acc[i][2] + bb, acc[i][3] + bb);
        *reinterpret_cast<float4*>(&C[(size_t)m * NSEQ + n0 + tx * 4]) = o;
    }
}

// ---------------------------------------------------------------------------
extern "C" void kernel_launch(void* const* d_in, const int* in_sizes, int n_in,
                              void* d_out, int out_size)
{
    const float* x    = (const float*)d_in[0];  // 16*32*128*128
    const float* Wq   = (const float*)d_in[1];  // 512*256
    const float* Wkv  = (const float*)d_in[2];  // 1024*256
    const float* Wout = (const float*)d_in[3];  // 256*512
    const float* bout = (const float*)d_in[4];  // 256
    float* out = (float*)d_out;

    (void)in_sizes; (void)n_in; (void)out_size;

    // 1) QKV projection
    {
        dim3 grid(NSEQ / 64, GQKV_M / 64, 2);
        gemm_qkv<<<grid, 256>>>(x, Wq, Wkv);
    }
    // 2) sim partials
    {
        dim3 grid(32, 16);
        sim_kernel<<<grid, 256>>>();
    }
    // 3) softmax
    {
        dim3 grid(64, 16);
        softmax_kernel<<<grid, 64>>>();
    }
    // 4) attn @ V
    {
        dim3 grid(NSEQ / 128, 16);
        outm_kernel<<<grid, 128>>>();
    }
    // 5) output projection + bias
    {
        dim3 grid(NSEQ / 64, 256 / 64, 2);
        gemm_out<<<grid, 256>>>(Wout, bout, out);
    }
}

// round 6
// speedup vs baseline: 1.6721x; 1.6721x over previous
#include <cuda_runtime.h>
#include <cuda_fp16.h>
#include <mma.h>
#include <cstdint>
#include <cstddef>

using namespace nvcuda;

// x: [16][32][128][128] fp32 == X[2][256][16384]
// Wq: [512][256], Wkv: [1024][256], Wout: [256][512], bout: [256]
// out: [2][256][16384] fp32
#define NSEQ 16384
#define GQKV_M 1536
#define SMS 80   // SMEM row stride in halves (160 B, 32B aligned rows)

// ------------------------------ scratch ------------------------------------
// __device__ globals referenced ONLY from device code.
__device__ float  g_qkv [(size_t)2 * 1536 * 16384];     // Q/K/V fp32
__device__ float  g_part[(size_t)16 * 32 * 64 * 64];    // sim partials
__device__ float  g_attn[(size_t)16 * 64 * 64];         // softmax(sim)
__device__ __half g_outmT_hi[(size_t)2 * 16384 * 512];  // (attn@V)^T hi
__device__ __half g_outmT_lo[(size_t)2 * 16384 * 512];  // (attn@V)^T lo
__device__ __half g_xt_hi[(size_t)2 * 16384 * 256];     // X^T hi
__device__ __half g_xt_lo[(size_t)2 * 16384 * 256];     // X^T lo
__device__ __half g_w_hi [(size_t)1536 * 256];          // [Wq;Wkv] hi
__device__ __half g_w_lo [(size_t)1536 * 256];          // [Wq;Wkv] lo
__device__ __half g_wout_hi[(size_t)256 * 512];         // Wout hi
__device__ __half g_wout_lo[(size_t)256 * 512];         // Wout lo

__device__ __forceinline__ void split_hl(float v, __half& hi, __half& lo) {
    hi = __float2half_rn(v);
    lo = __float2half_rn(v - __half2float(hi));
}

// ---------------------------------------------------------------------------
// Kernel A: weight conversion fp32 -> fp16 hi/lo
// ---------------------------------------------------------------------------
__global__ void convert_w(const float* __restrict__ Wq, const float* __restrict__ Wkv,
                          const float* __restrict__ Wout)
{
    int i = blockIdx.x * 256 + threadIdx.x;
    if (i < 1536 * 256) {
        float v = (i < 512 * 256) ? Wq[i] : Wkv[i - 512 * 256];
        split_hl(v, g_w_hi[i], g_w_lo[i]);
    }
    if (i < 256 * 512) split_hl(Wout[i], g_wout_hi[i], g_wout_lo[i]);
}

// ---------------------------------------------------------------------------
// Kernel B: X [g][256][16384] fp32 -> XT [g][16384][256] fp16 hi/lo
// ---------------------------------------------------------------------------
__global__ void __launch_bounds__(256) convert_x(const float* __restrict__ x)
{
    __shared__ float t[32][33];
    const int g  = blockIdx.z;
    const int n0 = blockIdx.x * 32;
    const int k0 = blockIdx.y * 32;
    const int tx = threadIdx.x, ty = threadIdx.y;
    const float* xg = x + (size_t)g * 256 * NSEQ;
#pragma unroll
    for (int r = 0; r < 32; r += 8)
        t[ty + r][tx] = xg[(size_t)(k0 + ty + r) * NSEQ + n0 + tx];
    __syncthreads();
    __half* hi = g_xt_hi + (size_t)g * NSEQ * 256;
    __half* lo = g_xt_lo + (size_t)g * NSEQ * 256;
#pragma unroll
    for (int r = 0; r < 32; r += 8) {
        const size_t o = (size_t)(n0 + ty + r) * 256 + k0 + tx;
        split_hl(t[tx][ty + r], hi[o], lo[o]);
    }
}

// ---------------------------------------------------------------------------
// wmma GEMM body (hi/lo compensated):
//   C = Ahi*Bhi + Ahi*Blo + Alo*Bhi  (+ bias[m])
// A*: [M][K] fp16 K-major, B*: [N][K] fp16 K-major, C fp32 row stride NSEQ.
// Block tile 128x128, 8 warps 2(m) x 4(n), warp tile 64x32.
// ---------------------------------------------------------------------------
__device__ __forceinline__ void hgemm_body(const __half* __restrict__ Ahi,
                                           const __half* __restrict__ Alo,
                                           const __half* __restrict__ Bhi,
                                           const __half* __restrict__ Blo,
                                           float* __restrict__ C,
                                           const float* __restrict__ bias,
                                           int K, size_t b_batch, size_t c_batch)
{
    __shared__ __align__(32) __half sA[128 * SMS];
    __shared__ __align__(32) __half sB[128 * SMS];
    __shared__ __align__(32) float  brep[128 * 16];

    const int tid = threadIdx.x;
    const int wid = tid >> 5;
    const int n0 = blockIdx.x * 128;
    const int m0 = blockIdx.y * 128;
    Bhi += (size_t)blockIdx.z * b_batch;
    Blo += (size_t)blockIdx.z * b_batch;
    C   += (size_t)blockIdx.z * c_batch;

    const int wm = wid >> 2;   // 0..1 -> 64 m-rows
    const int wn = wid & 3;    // 0..3 -> 32 n-cols

    for (int r = tid; r < 128; r += 256) {
        const float bv = bias ? bias[m0 + r] : 0.0f;
#pragma unroll
        for (int c = 0; c < 16; ++c) brep[r * 16 + c] = bv;
    }
    __syncthreads();

    wmma::fragment<wmma::accumulator, 16, 16, 16, float> acc[4][2];
#pragma unroll
    for (int mi = 0; mi < 4; ++mi)
#pragma unroll
        for (int ni = 0; ni < 2; ++ni)
            wmma::load_matrix_sync(acc[mi][ni],
                                   &brep[(wm * 64 + mi * 16) * 16], 16,
                                   wmma::mem_row_major);

    const int ldr = tid >> 3;   // 0..31
    const int ldc = tid & 7;    // 16B chunk 0..7

#pragma unroll 1
    for (int pass = 0; pass < 3; ++pass) {
        const __half* Ap = (pass == 2) ? Alo : Ahi;
        const __half* Bp = (pass == 1) ? Blo : Bhi;
#pragma unroll 1
        for (int kk = 0; kk < K; kk += 64) {
            __syncthreads();
#pragma unroll
            for (int it = 0; it < 4; ++it) {
                const int row = ldr + it * 32;
                *reinterpret_cast<uint4*>(&sA[row * SMS + ldc * 8]) =
                    *reinterpret_cast<const uint4*>(Ap + (size_t)(m0 + row) * K + kk + ldc * 8);
                *reinterpret_cast<uint4*>(&sB[row * SMS + ldc * 8]) =
                    *reinterpret_cast<const uint4*>(Bp + (size_t)(n0 + row) * K + kk + ldc * 8);
            }
            __syncthreads();

#pragma unroll
            for (int ks = 0; ks < 4; ++ks) {
                wmma::fragment<wmma::matrix_a, 16, 16, 16, __half, wmma::row_major> fa[4];
                wmma::fragment<wmma::matrix_b, 16, 16, 16, __half, wmma::col_major> fb[2];
#pragma unroll
                for (int mi = 0; mi < 4; ++mi)
                    wmma::load_matrix_sync(fa[mi], &sA[(wm * 64 + mi * 16) * SMS + ks * 16], SMS);
#pragma unroll
                for (int ni = 0; ni < 2; ++ni)
                    wmma::load_matrix_sync(fb[ni], &sB[(wn * 32 + ni * 16) * SMS + ks * 16], SMS);
#pragma unroll
                for (int mi = 0; mi < 4; ++mi)
#pragma unroll
                    for (int ni = 0; ni < 2; ++ni)
                        wmma::mma_sync(acc[mi][ni], fa[mi], fb[ni], acc[mi][ni]);
            }
        }
    }

#pragma unroll
    for (int mi = 0; mi < 4; ++mi)
#pragma unroll
        for (int ni = 0; ni < 2; ++ni)
            wmma::store_matrix_sync(
                C + (size_t)(m0 + wm * 64 + mi * 16) * NSEQ + n0 + wn * 32 + ni * 16,
                acc[mi][ni], NSEQ, wmma::mem_row_major);
}

// Wrappers bind scratch globals in DEVICE code.
__global__ void __launch_bounds__(256) hgemm_qkv()
{
    hgemm_body(g_w_hi, g_w_lo, g_xt_hi, g_xt_lo, g_qkv, nullptr,
               256, (size_t)NSEQ * 256, (size_t)GQKV_M * NSEQ);
}
__global__ void __launch_bounds__(256) hgemm_out(float* __restrict__ out,
                                                 const float* __restrict__ bout)
{
    hgemm_body(g_wout_hi, g_wout_lo, g_outmT_hi, g_outmT_lo, out, bout,
               512, (size_t)NSEQ * 512, (size_t)256 * NSEQ);
}

// ---------------------------------------------------------------------------
// Kernel D: sim partials (fp32 SIMT)
// ---------------------------------------------------------------------------
__global__ void __launch_bounds__(256) sim_kernel()
{
    const int ks = blockIdx.x;
    const int bh = blockIdx.y;
    const int g = bh >> 3, h = bh & 7;

    const float* Q = g_qkv + ((size_t)g * GQKV_M + h * 64) * NSEQ;
    const float* K = g_qkv + ((size_t)g * GQKV_M + 512 + h * 64) * NSEQ;
    const int p0 = ks * 512;

    __shared__ float Qs[16][64];
    __shared__ float Ks[16][64];

    const int tid = threadIdx.x;
    const int tx = tid & 15, ty = tid >> 4;
    const int lr = tid >> 2;
    const int lc = (tid & 3) * 4;

    float acc[4][4] = {};
    for (int pp = 0; pp < 512; pp += 16) {
        float4 qv = *reinterpret_cast<const float4*>(&Q[(size_t)lr * NSEQ + p0 + pp + lc]);
        float4 kv = *reinterpret_cast<const float4*>(&K[(size_t)lr * NSEQ + p0 + pp + lc]);
        __syncthreads();
        Qs[lc + 0][lr] = qv.x; Qs[lc + 1][lr] = qv.y;
        Qs[lc + 2][lr] = qv.z; Qs[lc + 3][lr] = qv.w;
        Ks[lc + 0][lr] = kv.x; Ks[lc + 1][lr] = kv.y;
        Ks[lc + 2][lr] = kv.z; Ks[lc + 3][lr] = kv.w;
        __syncthreads();
#pragma unroll
        for (int k = 0; k < 16; ++k) {
            float4 a = *reinterpret_cast<const float4*>(&Qs[k][ty * 4]);
            float4 b = *reinterpret_cast<const float4*>(&Ks[k][tx * 4]);
            float ra[4] = {a.x, a.y, a.z, a.w};
            float rb[4] = {b.x, b.y, b.z, b.w};
#pragma unroll
            for (int i = 0; i < 4; ++i)
#pragma unroll
                for (int j = 0; j < 4; ++j)
                    acc[i][j] = fmaf(ra[i], rb[j], acc[i][j]);
        }
    }
    float* P = g_part + (((size_t)bh * 32 + ks) * 64) * 64;
#pragma unroll
    for (int i = 0; i < 4; ++i) {
        float4 o = make_float4(acc[i][0], acc[i][1], acc[i][2], acc[i][3]);
        *reinterpret_cast<float4*>(&P[(size_t)(ty * 4 + i) * 64 + tx * 4]) = o;
    }
}

// ---------------------------------------------------------------------------
// Kernel E: reduce + softmax
// ---------------------------------------------------------------------------
__global__ void __launch_bounds__(64) softmax_kernel()
{
    const int i  = blockIdx.x;
    const int bh = blockIdx.y;
    const int j  = threadIdx.x;

    const float* P = g_part + (size_t)bh * 32 * 64 * 64;
    float v = 0.f;
#pragma unroll 8
    for (int ks = 0; ks < 32; ++ks)
        v += P[(size_t)(ks * 64 + i) * 64 + j];
    v *= 0.125f;

    __shared__ float s[64];
    __shared__ float red;
    s[j] = v;
    __syncthreads();
    if (j == 0) {
        float m = s[0];
        for (int t = 1; t < 64; ++t) m = fmaxf(m, s[t]);
        red = m;
    }
    __syncthreads();
    const float e = __expf(v - red);
    s[j] = e;
    __syncthreads();
    if (j == 0) {
        float su = 0.f;
        for (int t = 0; t < 64; ++t) su += s[t];
        red = su;
    }
    __syncthreads();
    g_attn[((size_t)bh * 64 + i) * 64 + j] = e / red;
}

// ---------------------------------------------------------------------------
// Kernel F: outm = attn@V, written TRANSPOSED fp16 hi/lo to g_outmT_*[g][p][h*64+i]
// ---------------------------------------------------------------------------
__global__ void __launch_bounds__(128) outm_kernel()
{
    const int bh = blockIdx.y;
    const int g = bh >> 3, h = bh & 7;
    const int p = blockIdx.x * 128 + threadIdx.x;

    __shared__ float a_s[64 * 64];
    const float* A = g_attn + (size_t)bh * 4096;
    for (int t = threadIdx.x; t < 4096; t += 128) a_s[t] = A[t];
    __syncthreads();

    const float* V = g_qkv + ((size_t)g * GQKV_M + 1024 + h * 64) * NSEQ;
    float v[64];
#pragma unroll
    for (int j = 0; j < 64; ++j) v[j] = V[(size_t)j * NSEQ + p];

    __half2 ohi[32], olo[32];
#pragma unroll 2
    for (int i2 = 0; i2 < 32; ++i2) {
        float acc0 = 0.f, acc1 = 0.f;
#pragma unroll
        for (int j = 0; j < 64; ++j) {
            acc0 = fmaf(a_s[(2 * i2 + 0) * 64 + j], v[j], acc0);
            acc1 = fmaf(a_s[(2 * i2 + 1) * 64 + j], v[j], acc1);
        }
        __half h0, l0, h1, l1;
        split_hl(acc0, h0, l0);
        split_hl(acc1, h1, l1);
        ohi[i2] = __halves2half2(h0, h1);
        olo[i2] = __halves2half2(l0, l1);
    }
    const size_t off = ((size_t)g * NSEQ + p) * 512 + h * 64;
    const uint4* shi = reinterpret_cast<const uint4*>(ohi);
    const uint4* slo = reinterpret_cast<const uint4*>(olo);
#pragma unroll
    for (int q = 0; q < 8; ++q) {
        reinterpret_cast<uint4*>(g_outmT_hi + off)[q] = shi[q];
        reinterpret_cast<uint4*>(g_outmT_lo + off)[q] = slo[q];
    }
}

// ---------------------------------------------------------------------------
extern "C" void kernel_launch(void* const* d_in, const int* in_sizes, int n_in,
                              void* d_out, int out_size)
{
    const float* x    = (const float*)d_in[0];
    const float* Wq   = (const float*)d_in[1];
    const float* Wkv  = (const float*)d_in[2];
    const float* Wout = (const float*)d_in[3];
    const float* bout = (const float*)d_in[4];
    float* out = (float*)d_out;
    (void)in_sizes; (void)n_in; (void)out_size;

    convert_w<<<1536, 256>>>(Wq, Wkv, Wout);
    {
        dim3 grid(NSEQ / 32, 256 / 32, 2);
        convert_x<<<grid, dim3(32, 8)>>>(x);
    }
    // QKV = [Wq;Wkv] @ X   (hi/lo compensated HMMA)
    {
        dim3 grid(NSEQ / 128, GQKV_M / 128, 2);
        hgemm_qkv<<<grid, 256>>>();
    }
    sim_kernel<<<dim3(32, 16), 256>>>();
    softmax_kernel<<<dim3(64, 16), 64>>>();
    outm_kernel<<<dim3(NSEQ / 128, 16), 128>>>();
    // out = Wout @ OutM + bout   (hi/lo compensated HMMA)
    {
        dim3 grid(NSEQ / 128, 256 / 128, 2);
        hgemm_out<<<grid, 256>>>(out, bout);
    }
}

// round 7
// speedup vs baseline: 2.0737x; 1.2401x over previous
#include <cuda_runtime.h>
#include <cuda_fp16.h>
#include <mma.h>
#include <cstdint>
#include <cstddef>

using namespace nvcuda;

// x: [16][32][128][128] fp32 == X[2][256][16384]
// Wq: [512][256], Wkv: [1024][256], Wout: [256][512], bout: [256]
// out: [2][256][16384] fp32
#define NSEQ 16384
#define GQKV_M 1536
#define SMS2 40   // SMEM row stride in halves for 32-wide K-chunks (80 B)

// ------------------------------ scratch ------------------------------------
// __device__ globals referenced ONLY from device code.
__device__ float  g_qkv [(size_t)2 * 1536 * 16384];     // Q/K/V fp32
__device__ float  g_part[(size_t)16 * 32 * 64 * 64];    // sim partials
__device__ float  g_attn[(size_t)16 * 64 * 64];         // softmax(sim)
__device__ __half g_outmT_hi[(size_t)2 * 16384 * 512];  // (attn@V)^T hi
__device__ __half g_outmT_lo[(size_t)2 * 16384 * 512];  // (attn@V)^T lo
__device__ __half g_xt_hi[(size_t)2 * 16384 * 256];     // X^T hi
__device__ __half g_xt_lo[(size_t)2 * 16384 * 256];     // X^T lo
__device__ __half g_w_hi [(size_t)1536 * 256];          // [Wq;Wkv] hi
__device__ __half g_w_lo [(size_t)1536 * 256];          // [Wq;Wkv] lo
__device__ __half g_wout_hi[(size_t)256 * 512];         // Wout hi
__device__ __half g_wout_lo[(size_t)256 * 512];         // Wout lo

__device__ __forceinline__ void split_hl(float v, __half& hi, __half& lo) {
    hi = __float2half_rn(v);
    lo = __float2half_rn(v - __half2float(hi));
}

// ---------------------------------------------------------------------------
// Kernel A: weight conversion fp32 -> fp16 hi/lo
// ---------------------------------------------------------------------------
__global__ void convert_w(const float* __restrict__ Wq, const float* __restrict__ Wkv,
                          const float* __restrict__ Wout)
{
    int i = blockIdx.x * 256 + threadIdx.x;
    if (i < 1536 * 256) {
        float v = (i < 512 * 256) ? Wq[i] : Wkv[i - 512 * 256];
        split_hl(v, g_w_hi[i], g_w_lo[i]);
    }
    if (i < 256 * 512) split_hl(Wout[i], g_wout_hi[i], g_wout_lo[i]);
}

// ---------------------------------------------------------------------------
// Kernel B: X [g][256][16384] fp32 -> XT [g][16384][256] fp16 hi/lo
// ---------------------------------------------------------------------------
__global__ void __launch_bounds__(256) convert_x(const float* __restrict__ x)
{
    __shared__ float t[32][33];
    const int g  = blockIdx.z;
    const int n0 = blockIdx.x * 32;
    const int k0 = blockIdx.y * 32;
    const int tx = threadIdx.x, ty = threadIdx.y;
    const float* xg = x + (size_t)g * 256 * NSEQ;
#pragma unroll
    for (int r = 0; r < 32; r += 8)
        t[ty + r][tx] = xg[(size_t)(k0 + ty + r) * NSEQ + n0 + tx];
    __syncthreads();
    __half* hi = g_xt_hi + (size_t)g * NSEQ * 256;
    __half* lo = g_xt_lo + (size_t)g * NSEQ * 256;
#pragma unroll
    for (int r = 0; r < 32; r += 8) {
        const size_t o = (size_t)(n0 + ty + r) * 256 + k0 + tx;
        split_hl(t[tx][ty + r], hi[o], lo[o]);
    }
}

// ---------------------------------------------------------------------------
// wmma GEMM body (hi/lo compensated, SHARED tile staging):
//   per K-chunk: load Ahi,Alo,Bhi,Blo tiles ONCE, then
//   acc += Ahi*Bhi + Ahi*Blo + Alo*Bhi
// A*: [M][K] fp16 K-major, B*: [N][K] fp16 K-major, C fp32 row stride NSEQ.
// Block tile 128x128, K-chunk 32. 8 warps 2(m) x 4(n), warp tile 64x32.
// Static SMEM: 4*128*40*2 + 128*16*4 = 49152 B (exactly 48 KB).
// ---------------------------------------------------------------------------
__device__ __forceinline__ void hgemm_body(const __half* __restrict__ Ahi,
                                           const __half* __restrict__ Alo,
                                           const __half* __restrict__ Bhi,
                                           const __half* __restrict__ Blo,
                                           float* __restrict__ C,
                                           const float* __restrict__ bias,
                                           int K, size_t b_batch, size_t c_batch)
{
    __shared__ __align__(32) __half sAh[128 * SMS2];
    __shared__ __align__(32) __half sAl[128 * SMS2];
    __shared__ __align__(32) __half sBh[128 * SMS2];
    __shared__ __align__(32) __half sBl[128 * SMS2];
    __shared__ __align__(32) float  brep[128 * 16];

    const int tid = threadIdx.x;
    const int wid = tid >> 5;
    const int n0 = blockIdx.x * 128;
    const int m0 = blockIdx.y * 128;
    Bhi += (size_t)blockIdx.z * b_batch;
    Blo += (size_t)blockIdx.z * b_batch;
    C   += (size_t)blockIdx.z * c_batch;

    const int wm = wid >> 2;   // 0..1 -> 64 m-rows
    const int wn = wid & 3;    // 0..3 -> 32 n-cols

    for (int r = tid; r < 128; r += 256) {
        const float bv = bias ? bias[m0 + r] : 0.0f;
#pragma unroll
        for (int c = 0; c < 16; ++c) brep[r * 16 + c] = bv;
    }
    __syncthreads();

    wmma::fragment<wmma::accumulator, 16, 16, 16, float> acc[4][2];
#pragma unroll
    for (int mi = 0; mi < 4; ++mi)
#pragma unroll
        for (int ni = 0; ni < 2; ++ni)
            wmma::load_matrix_sync(acc[mi][ni],
                                   &brep[(wm * 64 + mi * 16) * 16], 16,
                                   wmma::mem_row_major);

#pragma unroll 1
    for (int kk = 0; kk < K; kk += 32) {
        __syncthreads();
        // stage 4 tiles of 128 rows x 32 halves (each row = 4 uint4)
#pragma unroll
        for (int it = 0; it < 2; ++it) {
            const int idx = tid + it * 256;       // 0..511
            const int row = idx >> 2;             // 0..127
            const int c4  = idx & 3;              // uint4 index in row
            const size_t goff = (size_t)row * K + kk + c4 * 8;
            const int    soff = row * SMS2 + c4 * 8;
            *reinterpret_cast<uint4*>(&sAh[soff]) =
                *reinterpret_cast<const uint4*>(Ahi + (size_t)m0 * K + goff);
            *reinterpret_cast<uint4*>(&sAl[soff]) =
                *reinterpret_cast<const uint4*>(Alo + (size_t)m0 * K + goff);
            *reinterpret_cast<uint4*>(&sBh[soff]) =
                *reinterpret_cast<const uint4*>(Bhi + (size_t)n0 * K + goff);
            *reinterpret_cast<uint4*>(&sBl[soff]) =
                *reinterpret_cast<const uint4*>(Blo + (size_t)n0 * K + goff);
        }
        __syncthreads();

#pragma unroll
        for (int ks = 0; ks < 2; ++ks) {
            wmma::fragment<wmma::matrix_a, 16, 16, 16, __half, wmma::row_major> fah[4], fal[4];
            wmma::fragment<wmma::matrix_b, 16, 16, 16, __half, wmma::col_major> fbh[2], fbl[2];
#pragma unroll
            for (int mi = 0; mi < 4; ++mi) {
                const int ro = (wm * 64 + mi * 16) * SMS2 + ks * 16;
                wmma::load_matrix_sync(fah[mi], &sAh[ro], SMS2);
                wmma::load_matrix_sync(fal[mi], &sAl[ro], SMS2);
            }
#pragma unroll
            for (int ni = 0; ni < 2; ++ni) {
                const int ro = (wn * 32 + ni * 16) * SMS2 + ks * 16;
                wmma::load_matrix_sync(fbh[ni], &sBh[ro], SMS2);
                wmma::load_matrix_sync(fbl[ni], &sBl[ro], SMS2);
            }
#pragma unroll
            for (int mi = 0; mi < 4; ++mi)
#pragma unroll
                for (int ni = 0; ni < 2; ++ni) {
                    wmma::mma_sync(acc[mi][ni], fah[mi], fbh[ni], acc[mi][ni]);
                    wmma::mma_sync(acc[mi][ni], fah[mi], fbl[ni], acc[mi][ni]);
                    wmma::mma_sync(acc[mi][ni], fal[mi], fbh[ni], acc[mi][ni]);
                }
        }
    }

#pragma unroll
    for (int mi = 0; mi < 4; ++mi)
#pragma unroll
        for (int ni = 0; ni < 2; ++ni)
            wmma::store_matrix_sync(
                C + (size_t)(m0 + wm * 64 + mi * 16) * NSEQ + n0 + wn * 32 + ni * 16,
                acc[mi][ni], NSEQ, wmma::mem_row_major);
}

// Wrappers bind scratch globals in DEVICE code.
__global__ void __launch_bounds__(256) hgemm_qkv()
{
    hgemm_body(g_w_hi, g_w_lo, g_xt_hi, g_xt_lo, g_qkv, nullptr,
               256, (size_t)NSEQ * 256, (size_t)GQKV_M * NSEQ);
}
__global__ void __launch_bounds__(256) hgemm_out(float* __restrict__ out,
                                                 const float* __restrict__ bout)
{
    hgemm_body(g_wout_hi, g_wout_lo, g_outmT_hi, g_outmT_lo, out, bout,
               512, (size_t)NSEQ * 512, (size_t)256 * NSEQ);
}

// ---------------------------------------------------------------------------
// Kernel D: sim partials (fp32 SIMT)
// ---------------------------------------------------------------------------
__global__ void __launch_bounds__(256) sim_kernel()
{
    const int ks = blockIdx.x;
    const int bh = blockIdx.y;
    const int g = bh >> 3, h = bh & 7;

    const float* Q = g_qkv + ((size_t)g * GQKV_M + h * 64) * NSEQ;
    const float* K = g_qkv + ((size_t)g * GQKV_M + 512 + h * 64) * NSEQ;
    const int p0 = ks * 512;

    __shared__ float Qs[16][64];
    __shared__ float Ks[16][64];

    const int tid = threadIdx.x;
    const int tx = tid & 15, ty = tid >> 4;
    const int lr = tid >> 2;
    const int lc = (tid & 3) * 4;

    float acc[4][4] = {};
    for (int pp = 0; pp < 512; pp += 16) {
        float4 qv = *reinterpret_cast<const float4*>(&Q[(size_t)lr * NSEQ + p0 + pp + lc]);
        float4 kv = *reinterpret_cast<const float4*>(&K[(size_t)lr * NSEQ + p0 + pp + lc]);
        __syncthreads();
        Qs[lc + 0][lr] = qv.x; Qs[lc + 1][lr] = qv.y;
        Qs[lc + 2][lr] = qv.z; Qs[lc + 3][lr] = qv.w;
        Ks[lc + 0][lr] = kv.x; Ks[lc + 1][lr] = kv.y;
        Ks[lc + 2][lr] = kv.z; Ks[lc + 3][lr] = kv.w;
        __syncthreads();
#pragma unroll
        for (int k = 0; k < 16; ++k) {
            float4 a = *reinterpret_cast<const float4*>(&Qs[k][ty * 4]);
            float4 b = *reinterpret_cast<const float4*>(&Ks[k][tx * 4]);
            float ra[4] = {a.x, a.y, a.z, a.w};
            float rb[4] = {b.x, b.y, b.z, b.w};
#pragma unroll
            for (int i = 0; i < 4; ++i)
#pragma unroll
                for (int j = 0; j < 4; ++j)
                    acc[i][j] = fmaf(ra[i], rb[j], acc[i][j]);
        }
    }
    float* P = g_part + (((size_t)bh * 32 + ks) * 64) * 64;
#pragma unroll
    for (int i = 0; i < 4; ++i) {
        float4 o = make_float4(acc[i][0], acc[i][1], acc[i][2], acc[i][3]);
        *reinterpret_cast<float4*>(&P[(size_t)(ty * 4 + i) * 64 + tx * 4]) = o;
    }
}

// ---------------------------------------------------------------------------
// Kernel E: reduce + softmax
// ---------------------------------------------------------------------------
__global__ void __launch_bounds__(64) softmax_kernel()
{
    const int i  = blockIdx.x;
    const int bh = blockIdx.y;
    const int j  = threadIdx.x;

    const float* P = g_part + (size_t)bh * 32 * 64 * 64;
    float v = 0.f;
#pragma unroll 8
    for (int ks = 0; ks < 32; ++ks)
        v += P[(size_t)(ks * 64 + i) * 64 + j];
    v *= 0.125f;

    __shared__ float s[64];
    __shared__ float red;
    s[j] = v;
    __syncthreads();
    if (j == 0) {
        float m = s[0];
        for (int t = 1; t < 64; ++t) m = fmaxf(m, s[t]);
        red = m;
    }
    __syncthreads();
    const float e = __expf(v - red);
    s[j] = e;
    __syncthreads();
    if (j == 0) {
        float su = 0.f;
        for (int t = 0; t < 64; ++t) su += s[t];
        red = su;
    }
    __syncthreads();
    g_attn[((size_t)bh * 64 + i) * 64 + j] = e / red;
}

// ---------------------------------------------------------------------------
// Kernel F: outm = attn@V, written TRANSPOSED fp16 hi/lo to g_outmT_*[g][p][h*64+i]
// ---------------------------------------------------------------------------
__global__ void __launch_bounds__(128) outm_kernel()
{
    const int bh = blockIdx.y;
    const int g = bh >> 3, h = bh & 7;
    const int p = blockIdx.x * 128 + threadIdx.x;

    __shared__ float a_s[64 * 64];
    const float* A = g_attn + (size_t)bh * 4096;
    for (int t = threadIdx.x; t < 4096; t += 128) a_s[t] = A[t];
    __syncthreads();

    const float* V = g_qkv + ((size_t)g * GQKV_M + 1024 + h * 64) * NSEQ;
    float v[64];
#pragma unroll
    for (int j = 0; j < 64; ++j) v[j] = V[(size_t)j * NSEQ + p];

    __half2 ohi[32], olo[32];
#pragma unroll 2
    for (int i2 = 0; i2 < 32; ++i2) {
        float acc0 = 0.f, acc1 = 0.f;
#pragma unroll
        for (int j = 0; j < 64; ++j) {
            acc0 = fmaf(a_s[(2 * i2 + 0) * 64 + j], v[j], acc0);
            acc1 = fmaf(a_s[(2 * i2 + 1) * 64 + j], v[j], acc1);
        }
        __half h0, l0, h1, l1;
        split_hl(acc0, h0, l0);
        split_hl(acc1, h1, l1);
        ohi[i2] = __halves2half2(h0, h1);
        olo[i2] = __halves2half2(l0, l1);
    }
    const size_t off = ((size_t)g * NSEQ + p) * 512 + h * 64;
    const uint4* shi = reinterpret_cast<const uint4*>(ohi);
    const uint4* slo = reinterpret_cast<const uint4*>(olo);
#pragma unroll
    for (int q = 0; q < 8; ++q) {
        reinterpret_cast<uint4*>(g_outmT_hi + off)[q] = shi[q];
        reinterpret_cast<uint4*>(g_outmT_lo + off)[q] = slo[q];
    }
}

// ---------------------------------------------------------------------------
extern "C" void kernel_launch(void* const* d_in, const int* in_sizes, int n_in,
                              void* d_out, int out_size)
{
    const float* x    = (const float*)d_in[0];
    const float* Wq   = (const float*)d_in[1];
    const float* Wkv  = (const float*)d_in[2];
    const float* Wout = (const float*)d_in[3];
    const float* bout = (const float*)d_in[4];
    float* out = (float*)d_out;
    (void)in_sizes; (void)n_in; (void)out_size;

    convert_w<<<1536, 256>>>(Wq, Wkv, Wout);
    {
        dim3 grid(NSEQ / 32, 256 / 32, 2);
        convert_x<<<grid, dim3(32, 8)>>>(x);
    }
    // QKV = [Wq;Wkv] @ X   (hi/lo compensated HMMA, shared staging)
    {
        dim3 grid(NSEQ / 128, GQKV_M / 128, 2);
        hgemm_qkv<<<grid, 256>>>();
    }
    sim_kernel<<<dim3(32, 16), 256>>>();
    softmax_kernel<<<dim3(64, 16), 64>>>();
    outm_kernel<<<dim3(NSEQ / 128, 16), 128>>>();
    // out = Wout @ OutM + bout   (hi/lo compensated HMMA, shared staging)
    {
        dim3 grid(NSEQ / 128, 256 / 128, 2);
        hgemm_out<<<grid, 256>>>(out, bout);
    }
}